// round 9
// baseline (speedup 1.0000x reference)
#include <cuda_runtime.h>
#include <stdint.h>

#define W 4096
#define H 4096
#define NPIX (W*H)
#define TS 32
#define XS 40   // TS + 2*4 (sobel halo 1 + gauss halo 3)
#define PS 38   // TS + 2*3
#define RANK0 8388607u  // (NPIX-1)/2

// ---------------- device scratch (no allocations allowed) ----------------
__device__ float g_R[NPIX];                  // Harris response, 64MB
__device__ unsigned int g_cand[NPIX];        // pass-2 candidate keys, 64MB
__device__ unsigned int g_ncand;
__device__ unsigned int g_hist1[2048];
__device__ unsigned int g_hist2[2048];
__device__ unsigned int g_hist3[1024];
__device__ unsigned int g_bin1, g_bin2;
__device__ unsigned int g_rka, g_rkb;
__device__ float g_med;

__constant__ float c_gw[49];                 // Gaussian weights (copied from gk)

// monotone float -> uint key (ascending IEEE order)
__device__ __forceinline__ unsigned int fkey(float f) {
    unsigned int u = __float_as_uint(f);
    return (u & 0x80000000u) ? ~u : (u | 0x80000000u);
}
__device__ __forceinline__ float keyf(unsigned int k) {
    unsigned int u = (k & 0x80000000u) ? (k & 0x7FFFFFFFu) : ~k;
    return __uint_as_float(u);
}

// ---------------- init: zero histograms (graph replays must reset) -------
__global__ void init_kernel() {
    int t = blockIdx.x * blockDim.x + threadIdx.x;
    if (t < 2048) { g_hist1[t] = 0u; g_hist2[t] = 0u; }
    if (t < 1024) g_hist3[t] = 0u;
    if (t == 0) g_ncand = 0u;
}

// ---------------- K1: Sobel + products + direct 7x7 Gaussian + R ---------
// Numerics mimic XLA-CPU/Eigen: per-output sequential FMA chain over taps in
// row-major (kh outer, kw inner) order; elementwise ops with explicit _rn
// intrinsics. Weights bitwise from gk via __constant__ (LDCU, uniform port).
__global__ __launch_bounds__(256) void harris_R_kernel(
    const float* __restrict__ x)
{
    __shared__ float xs[XS][XS];
    __shared__ float pch[3][PS][PS];
    __shared__ unsigned int shist[2048];

    const int tid  = threadIdx.y * 32 + threadIdx.x;
    const int lane = threadIdx.x;
    const int bx0 = blockIdx.x * TS, by0 = blockIdx.y * TS;

    for (int i = tid; i < 2048; i += 256) shist[i] = 0u;

    // load x tile with halo 4, zero outside image (conv zero padding)
    for (int i = tid; i < XS * XS; i += 256) {
        int r = i / XS, c = i % XS;
        int gr = by0 - 4 + r, gc = bx0 - 4 + c;
        float v = 0.f;
        if (gr >= 0 && gr < H && gc >= 0 && gc < W) v = x[gr * W + gc];
        xs[r][c] = v;
    }
    __syncthreads();

    // Sobel (sequential row-major tap chains) + products over tile + halo 3.
    for (int i = tid; i < PS * PS; i += 256) {
        int pr = i / PS, pc = i % PS;
        int gr = by0 - 3 + pr, gc = bx0 - 3 + pc;
        float a = 0.f, b = 0.f, ab = 0.f;
        if (gr >= 0 && gr < H && gc >= 0 && gc < W) {
            int r = pr + 1, c = pc + 1;
            float x00 = xs[r-1][c-1], x01 = xs[r-1][c], x02 = xs[r-1][c+1];
            float x10 = xs[r  ][c-1],                  x12 = xs[r  ][c+1];
            float x20 = xs[r+1][c-1], x21 = xs[r+1][c], x22 = xs[r+1][c+1];
            float ix = -x00;
            ix = __fmaf_rn( 1.f, x02, ix);
            ix = __fmaf_rn(-2.f, x10, ix);
            ix = __fmaf_rn( 2.f, x12, ix);
            ix = __fmaf_rn(-1.f, x20, ix);
            ix = __fmaf_rn( 1.f, x22, ix);
            float iy = -x00;
            iy = __fmaf_rn(-2.f, x01, iy);
            iy = __fmaf_rn(-1.f, x02, iy);
            iy = __fmaf_rn( 1.f, x20, iy);
            iy = __fmaf_rn( 2.f, x21, iy);
            iy = __fmaf_rn( 1.f, x22, iy);
            a  = __fmul_rn(ix, ix);
            b  = __fmul_rn(iy, iy);
            ab = __fmul_rn(ix, iy);
        }
        pch[0][pr][pc] = a; pch[1][pr][pc] = b; pch[2][pr][pc] = ab;
    }
    __syncthreads();

    // Direct 7x7 conv, 4 output rows per thread, 5-slot prefetch ring.
    // Chain per output: kh outer (0..6), kw inner (0..6) — sequential FMAs.
    const int co = threadIdx.x;
    const int ro = threadIdx.y * 4;
    float S[3][4];

    #pragma unroll
    for (int ch = 0; ch < 3; ch++) {
        float acc[4] = {0.f, 0.f, 0.f, 0.f};
        float rb[5][7];
        #pragma unroll
        for (int o = 0; o < 4; o++)
            #pragma unroll
            for (int k = 0; k < 7; k++)
                rb[o][k] = pch[ch][ro + o][co + k];

        #pragma unroll
        for (int kh = 0; kh < 7; kh++) {
            if (kh < 6) {   // prefetch row kh+4 (used at kh+1)
                const int slot = (kh + 4) % 5;
                #pragma unroll
                for (int k = 0; k < 7; k++)
                    rb[slot][k] = pch[ch][ro + kh + 4][co + k];
            }
            #pragma unroll
            for (int kw = 0; kw < 7; kw++) {
                const float w = c_gw[kh * 7 + kw];   // uniform const load
                #pragma unroll
                for (int o = 0; o < 4; o++)
                    acc[o] = __fmaf_rn(w, rb[(kh + o) % 5][kw], acc[o]);
            }
        }
        #pragma unroll
        for (int o = 0; o < 4; o++) S[ch][o] = acc[o];
    }

    #pragma unroll
    for (int o = 0; o < 4; o++) {
        float s0 = S[0][o], s1 = S[1][o], s2 = S[2][o];
        float tr = __fadd_rn(s0, s1);
        float t1 = __fmul_rn(s0, s1);
        float t2 = __fmul_rn(s2, s2);
        float t3 = __fmul_rn(__fmul_rn(0.05f, tr), tr);
        float R  = __fsub_rn(__fsub_rn(t1, t2), t3);
        g_R[(by0 + ro + o) * W + bx0 + co] = R;
        // warp-aggregated histogram atomic
        unsigned int bin = fkey(R) >> 21;
        unsigned int mm = __match_any_sync(0xffffffffu, bin);
        int leader = __ffs(mm) - 1;
        if (lane == leader) atomicAdd(&shist[bin], (unsigned int)__popc(mm));
    }
    __syncthreads();
    for (int i = tid; i < 2048; i += 256) {
        unsigned int v = shist[i];
        if (v) atomicAdd(&g_hist1[i], v);
    }
}

// ---------------- pass 2: histogram bits[20:10] + compact candidates -----
#define H2_BLOCKS 2048
#define H2_IPT 8     // float4 iters per thread: 2048*256*8*4 = 16.7M
__global__ __launch_bounds__(256) void hist2_kernel() {
    __shared__ unsigned int sh[2048];
    const int tid = threadIdx.x;
    const int lane = tid & 31;
    for (int i = tid; i < 2048; i += 256) sh[i] = 0u;
    __syncthreads();
    const unsigned int b1 = g_bin1;
    const float4* R4 = (const float4*)g_R;
    const int base = blockIdx.x * (256 * H2_IPT) + tid;

    float4 v[H2_IPT];
    #pragma unroll
    for (int j = 0; j < H2_IPT; j++) v[j] = R4[base + j * 256];

    #pragma unroll
    for (int j = 0; j < H2_IPT; j++) {
        float e[4] = {v[j].x, v[j].y, v[j].z, v[j].w};
        #pragma unroll
        for (int c = 0; c < 4; c++) {
            unsigned int k = fkey(e[c]);
            bool match = ((k >> 21) == b1);
            unsigned int m = __ballot_sync(0xffffffffu, match);
            if (m) {
                if (match) atomicAdd(&sh[(k >> 10) & 2047u], 1u);
                unsigned int pos0 = 0u;
                int leader = __ffs(m) - 1;
                if (lane == leader)
                    pos0 = atomicAdd(&g_ncand, (unsigned int)__popc(m));
                pos0 = __shfl_sync(0xffffffffu, pos0, leader);
                if (match)
                    g_cand[pos0 + __popc(m & ((1u << lane) - 1u))] = k;
            }
        }
    }
    __syncthreads();
    for (int i = tid; i < 2048; i += 256) {
        unsigned int c = sh[i];
        if (c) atomicAdd(&g_hist2[i], c);
    }
}

// ---------------- pass 3: histogram low 10 bits over candidates ----------
__global__ __launch_bounds__(256) void hist3_kernel() {
    __shared__ unsigned int sh[1024];
    const int tid = threadIdx.x;
    for (int i = tid; i < 1024; i += 256) sh[i] = 0u;
    __syncthreads();
    const unsigned int p22 = (g_bin1 << 11) | g_bin2;
    const unsigned int n = g_ncand;
    for (unsigned int i = blockIdx.x * blockDim.x + tid; i < n;
         i += gridDim.x * blockDim.x) {
        unsigned int k = g_cand[i];
        if ((k >> 10) == p22) atomicAdd(&sh[k & 1023u], 1u);
    }
    __syncthreads();
    for (int i = tid; i < 1024; i += 256) {
        unsigned int c = sh[i];
        if (c) atomicAdd(&g_hist3[i], c);
    }
}

// scan a histogram in parallel, select the bin containing the residual rank
__global__ __launch_bounds__(1024) void scan_select_kernel(int pass) {
    __shared__ unsigned int ss[1024];
    int t = threadIdx.x;
    const unsigned int* hist;
    int nbins;
    if (pass == 1)      { hist = g_hist1; nbins = 2048; }
    else if (pass == 2) { hist = g_hist2; nbins = 2048; }
    else                { hist = g_hist3; nbins = 1024; }
    int bpt = nbins >> 10;  // 2 or 1
    unsigned int local = 0u;
    for (int i = 0; i < bpt; i++) local += hist[t * bpt + i];
    ss[t] = local;
    __syncthreads();
    for (int off = 1; off < 1024; off <<= 1) {
        unsigned int v = (t >= off) ? ss[t - off] : 0u;
        __syncthreads();
        ss[t] += v;
        __syncthreads();
    }
    unsigned int rank = (pass == 1) ? RANK0 : ((pass == 2) ? g_rka : g_rkb);
    unsigned int cb = (t == 0) ? 0u : ss[t - 1];
    for (int i = 0; i < bpt; i++) {
        unsigned int hv = hist[t * bpt + i];
        if (rank >= cb && rank < cb + hv) {
            unsigned int bin = (unsigned int)(t * bpt + i);
            if (pass == 1)      { g_bin1 = bin; g_rka = rank - cb; }
            else if (pass == 2) { g_bin2 = bin; g_rkb = rank - cb; }
            else {
                unsigned int key = (g_bin1 << 21) | (g_bin2 << 10) | bin;
                g_med = keyf(key);
            }
        }
        cb += hv;
    }
}

// ---------------- threshold + 7x7 max-pool NMS ---------------------------
#define MS 38
__global__ __launch_bounds__(256) void nms_kernel(float* __restrict__ out) {
    __shared__ float rts[MS][MS + 1];
    __shared__ float hm[MS][TS];
    const int tid = threadIdx.y * 32 + threadIdx.x;
    const int bx0 = blockIdx.x * TS, by0 = blockIdx.y * TS;
    const float med = g_med;
    const float NEGINF = __int_as_float(0xff800000);

    for (int i = tid; i < MS * MS; i += 256) {
        int r = i / MS, c = i % MS;
        int gr = by0 - 3 + r, gc = bx0 - 3 + c;
        float v = NEGINF;
        if (gr >= 0 && gr < H && gc >= 0 && gc < W) {
            float R = g_R[gr * W + gc];
            v = (R < med) ? 0.f : R;
        }
        rts[r][c] = v;
    }
    __syncthreads();

    for (int i = tid; i < MS * TS; i += 256) {
        int r = i / TS, co = i % TS;
        float m = rts[r][co];
        #pragma unroll
        for (int k = 1; k < 7; k++) m = fmaxf(m, rts[r][co + k]);
        hm[r][co] = m;
    }
    __syncthreads();

    for (int ro = threadIdx.y; ro < TS; ro += 8) {
        int co = threadIdx.x;
        float m = hm[ro][co];
        #pragma unroll
        for (int k = 1; k < 7; k++) m = fmaxf(m, hm[ro + k][co]);
        float c = rts[ro + 3][co + 3];
        out[(by0 + ro) * W + bx0 + co] = (c == m) ? c : 0.f;
    }
}

// ---------------- launcher ------------------------------------------------
extern "C" void kernel_launch(void* const* d_in, const int* in_sizes, int n_in,
                              void* d_out, int out_size) {
    const float* x  = (const float*)d_in[0];
    const float* gk = (const float*)d_in[1];
    float* out = (float*)d_out;

    dim3 blk(32, 8);
    dim3 grd(W / TS, H / TS);

    cudaMemcpyToSymbolAsync(c_gw, gk, 49 * sizeof(float), 0,
                            cudaMemcpyDeviceToDevice);
    init_kernel<<<2, 1024>>>();
    harris_R_kernel<<<grd, blk>>>(x);
    scan_select_kernel<<<1, 1024>>>(1);
    hist2_kernel<<<H2_BLOCKS, 256>>>();
    scan_select_kernel<<<1, 1024>>>(2);
    hist3_kernel<<<256, 256>>>();
    scan_select_kernel<<<1, 1024>>>(3);
    nms_kernel<<<grd, blk>>>(out);
}

// round 10
// speedup vs baseline: 2.0037x; 2.0037x over previous
#include <cuda_runtime.h>
#include <stdint.h>

#define W 4096
#define H 4096
#define NPIX (W*H)
#define TS 32
#define XS 40   // TS + 2*4 (sobel halo 1 + gauss halo 3)
#define PS 38   // TS + 2*3
#define RANK0 8388607u  // (NPIX-1)/2
#define K1_THREADS 128

// ---------------- device scratch (no allocations allowed) ----------------
__device__ float g_R[NPIX];                 // Harris response, 64MB
__device__ unsigned int g_hist1[2048];
__device__ unsigned int g_hist2[2048];
__device__ unsigned int g_hist3[1024];
__device__ unsigned int g_bin1, g_bin2;
__device__ unsigned int g_rka, g_rkb;
__device__ float g_med;

// monotone float -> uint key (ascending IEEE order)
__device__ __forceinline__ unsigned int fkey(float f) {
    unsigned int u = __float_as_uint(f);
    return (u & 0x80000000u) ? ~u : (u | 0x80000000u);
}
__device__ __forceinline__ float keyf(unsigned int k) {
    unsigned int u = (k & 0x80000000u) ? (k & 0x7FFFFFFFu) : ~k;
    return __uint_as_float(u);
}

// ---------------- init: zero histograms (graph replays must reset) -------
__global__ void init_kernel() {
    int t = blockIdx.x * blockDim.x + threadIdx.x;
    if (t < 2048) { g_hist1[t] = 0u; g_hist2[t] = 0u; }
    if (t < 1024) g_hist3[t] = 0u;
}

// ---------------- K1: Sobel + products + direct 7x7 Gaussian + R ---------
// Numerics mimic XLA-CPU/Eigen: per-output sequential FMA chain over taps in
// row-major (kh outer, kw inner) order; elementwise ops with explicit _rn
// intrinsics. Weights bitwise from gk (smem). 8 output rows per thread,
// 9-slot sliding register ring -> 8 independent FMA chains per thread.
__global__ __launch_bounds__(K1_THREADS) void harris_R_kernel(
    const float* __restrict__ x, const float* __restrict__ gk)
{
    __shared__ float xs[XS][XS];
    __shared__ float pch[3][PS][PS];
    __shared__ float gws[49];
    __shared__ unsigned int shist[2048];

    const int tid = threadIdx.y * 32 + threadIdx.x;
    const int bx0 = blockIdx.x * TS, by0 = blockIdx.y * TS;

    for (int i = tid; i < 2048; i += K1_THREADS) shist[i] = 0u;
    if (tid < 49) gws[tid] = gk[tid];

    // load x tile with halo 4, zero outside image (conv zero padding)
    for (int i = tid; i < XS * XS; i += K1_THREADS) {
        int r = i / XS, c = i % XS;
        int gr = by0 - 4 + r, gc = bx0 - 4 + c;
        float v = 0.f;
        if (gr >= 0 && gr < H && gc >= 0 && gc < W) v = x[gr * W + gc];
        xs[r][c] = v;
    }
    __syncthreads();

    // Sobel (sequential row-major tap chains) + products over tile + halo 3.
    for (int i = tid; i < PS * PS; i += K1_THREADS) {
        int pr = i / PS, pc = i % PS;
        int gr = by0 - 3 + pr, gc = bx0 - 3 + pc;
        float a = 0.f, b = 0.f, ab = 0.f;
        if (gr >= 0 && gr < H && gc >= 0 && gc < W) {
            int r = pr + 1, c = pc + 1;
            float x00 = xs[r-1][c-1], x01 = xs[r-1][c], x02 = xs[r-1][c+1];
            float x10 = xs[r  ][c-1],                  x12 = xs[r  ][c+1];
            float x20 = xs[r+1][c-1], x21 = xs[r+1][c], x22 = xs[r+1][c+1];
            float ix = -x00;
            ix = __fmaf_rn( 1.f, x02, ix);
            ix = __fmaf_rn(-2.f, x10, ix);
            ix = __fmaf_rn( 2.f, x12, ix);
            ix = __fmaf_rn(-1.f, x20, ix);
            ix = __fmaf_rn( 1.f, x22, ix);
            float iy = -x00;
            iy = __fmaf_rn(-2.f, x01, iy);
            iy = __fmaf_rn(-1.f, x02, iy);
            iy = __fmaf_rn( 1.f, x20, iy);
            iy = __fmaf_rn( 2.f, x21, iy);
            iy = __fmaf_rn( 1.f, x22, iy);
            a  = __fmul_rn(ix, ix);
            b  = __fmul_rn(iy, iy);
            ab = __fmul_rn(ix, iy);
        }
        pch[0][pr][pc] = a; pch[1][pr][pc] = b; pch[2][pr][pc] = ab;
    }
    __syncthreads();

    // Direct 7x7 conv, 8 output rows per thread, 9-slot sliding ring.
    // Chain per output: kh outer (0..6), kw inner (0..6) — sequential FMAs.
    const int co = threadIdx.x;
    const int ro = threadIdx.y * 8;     // ty in 0..3 -> rows 0..31
    float S01[2][8];

    #pragma unroll
    for (int ch = 0; ch < 3; ch++) {
        float acc[8] = {0.f, 0.f, 0.f, 0.f, 0.f, 0.f, 0.f, 0.f};
        float rb[9][7];
        // initial fill: rows ro..ro+7 -> slots 0..7
        #pragma unroll
        for (int o = 0; o < 8; o++)
            #pragma unroll
            for (int k = 0; k < 7; k++)
                rb[o][k] = pch[ch][ro + o][co + k];

        #pragma unroll
        for (int kh = 0; kh < 7; kh++) {
            if (kh < 6) {   // prefetch row ro+kh+8 into slot (kh+8)%9
                const int slot = (kh + 8) % 9;
                #pragma unroll
                for (int k = 0; k < 7; k++)
                    rb[slot][k] = pch[ch][ro + kh + 8][co + k];
            }
            #pragma unroll
            for (int kw = 0; kw < 7; kw++) {
                const float w = gws[kh * 7 + kw];
                #pragma unroll
                for (int o = 0; o < 8; o++)
                    acc[o] = __fmaf_rn(w, rb[(kh + o) % 9][kw], acc[o]);
            }
        }

        if (ch < 2) {
            #pragma unroll
            for (int o = 0; o < 8; o++) S01[ch][o] = acc[o];
        } else {
            // ch2 done: compute R per output immediately (acc = s2)
            #pragma unroll
            for (int o = 0; o < 8; o++) {
                float s0 = S01[0][o], s1 = S01[1][o], s2 = acc[o];
                float tr = __fadd_rn(s0, s1);
                float t1 = __fmul_rn(s0, s1);
                float t2 = __fmul_rn(s2, s2);
                float t3 = __fmul_rn(__fmul_rn(0.05f, tr), tr);
                float R  = __fsub_rn(__fsub_rn(t1, t2), t3);
                g_R[(by0 + ro + o) * W + bx0 + co] = R;
                atomicAdd(&shist[fkey(R) >> 21], 1u);
            }
        }
    }
    __syncthreads();
    for (int i = tid; i < 2048; i += K1_THREADS) {
        unsigned int v = shist[i];
        if (v) atomicAdd(&g_hist1[i], v);
    }
}

// ---------------- median radix-select passes -----------------------------
__global__ __launch_bounds__(256) void hist2_kernel() {
    __shared__ unsigned int sh[2048];
    int tid = threadIdx.x;
    for (int i = tid; i < 2048; i += 256) sh[i] = 0u;
    __syncthreads();
    unsigned int b1 = g_bin1;
    const float4* R4 = (const float4*)g_R;
    int n4 = NPIX / 4;
    for (int i = blockIdx.x * blockDim.x + tid; i < n4; i += gridDim.x * blockDim.x) {
        float4 v = R4[i];
        unsigned int k;
        k = fkey(v.x); if ((k >> 21) == b1) atomicAdd(&sh[(k >> 10) & 2047u], 1u);
        k = fkey(v.y); if ((k >> 21) == b1) atomicAdd(&sh[(k >> 10) & 2047u], 1u);
        k = fkey(v.z); if ((k >> 21) == b1) atomicAdd(&sh[(k >> 10) & 2047u], 1u);
        k = fkey(v.w); if ((k >> 21) == b1) atomicAdd(&sh[(k >> 10) & 2047u], 1u);
    }
    __syncthreads();
    for (int i = tid; i < 2048; i += 256) {
        unsigned int v = sh[i];
        if (v) atomicAdd(&g_hist2[i], v);
    }
}

__global__ __launch_bounds__(256) void hist3_kernel() {
    __shared__ unsigned int sh[1024];
    int tid = threadIdx.x;
    for (int i = tid; i < 1024; i += 256) sh[i] = 0u;
    __syncthreads();
    unsigned int p22 = (g_bin1 << 11) | g_bin2;
    const float4* R4 = (const float4*)g_R;
    int n4 = NPIX / 4;
    for (int i = blockIdx.x * blockDim.x + tid; i < n4; i += gridDim.x * blockDim.x) {
        float4 v = R4[i];
        unsigned int k;
        k = fkey(v.x); if ((k >> 10) == p22) atomicAdd(&sh[k & 1023u], 1u);
        k = fkey(v.y); if ((k >> 10) == p22) atomicAdd(&sh[k & 1023u], 1u);
        k = fkey(v.z); if ((k >> 10) == p22) atomicAdd(&sh[k & 1023u], 1u);
        k = fkey(v.w); if ((k >> 10) == p22) atomicAdd(&sh[k & 1023u], 1u);
    }
    __syncthreads();
    for (int i = tid; i < 1024; i += 256) {
        unsigned int v = sh[i];
        if (v) atomicAdd(&g_hist3[i], v);
    }
}

// scan a histogram in parallel, select the bin containing the residual rank
__global__ __launch_bounds__(1024) void scan_select_kernel(int pass) {
    __shared__ unsigned int ss[1024];
    int t = threadIdx.x;
    const unsigned int* hist;
    int nbins;
    if (pass == 1)      { hist = g_hist1; nbins = 2048; }
    else if (pass == 2) { hist = g_hist2; nbins = 2048; }
    else                { hist = g_hist3; nbins = 1024; }
    int bpt = nbins >> 10;  // 2 or 1
    unsigned int local = 0u;
    for (int i = 0; i < bpt; i++) local += hist[t * bpt + i];
    ss[t] = local;
    __syncthreads();
    for (int off = 1; off < 1024; off <<= 1) {
        unsigned int v = (t >= off) ? ss[t - off] : 0u;
        __syncthreads();
        ss[t] += v;
        __syncthreads();
    }
    unsigned int rank = (pass == 1) ? RANK0 : ((pass == 2) ? g_rka : g_rkb);
    unsigned int cb = (t == 0) ? 0u : ss[t - 1];
    for (int i = 0; i < bpt; i++) {
        unsigned int hv = hist[t * bpt + i];
        if (rank >= cb && rank < cb + hv) {
            unsigned int bin = (unsigned int)(t * bpt + i);
            if (pass == 1)      { g_bin1 = bin; g_rka = rank - cb; }
            else if (pass == 2) { g_bin2 = bin; g_rkb = rank - cb; }
            else {
                unsigned int key = (g_bin1 << 21) | (g_bin2 << 10) | bin;
                g_med = keyf(key);
            }
        }
        cb += hv;
    }
}

// ---------------- threshold + 7x7 max-pool NMS ---------------------------
#define MS 38
__global__ __launch_bounds__(256) void nms_kernel(float* __restrict__ out) {
    __shared__ float rts[MS][MS + 1];
    __shared__ float hm[MS][TS];
    const int tid = threadIdx.y * 32 + threadIdx.x;
    const int bx0 = blockIdx.x * TS, by0 = blockIdx.y * TS;
    const float med = g_med;
    const float NEGINF = __int_as_float(0xff800000);

    for (int i = tid; i < MS * MS; i += 256) {
        int r = i / MS, c = i % MS;
        int gr = by0 - 3 + r, gc = bx0 - 3 + c;
        float v = NEGINF;
        if (gr >= 0 && gr < H && gc >= 0 && gc < W) {
            float R = g_R[gr * W + gc];
            v = (R < med) ? 0.f : R;
        }
        rts[r][c] = v;
    }
    __syncthreads();

    for (int i = tid; i < MS * TS; i += 256) {
        int r = i / TS, co = i % TS;
        float m = rts[r][co];
        #pragma unroll
        for (int k = 1; k < 7; k++) m = fmaxf(m, rts[r][co + k]);
        hm[r][co] = m;
    }
    __syncthreads();

    for (int ro = threadIdx.y; ro < TS; ro += 8) {
        int co = threadIdx.x;
        float m = hm[ro][co];
        #pragma unroll
        for (int k = 1; k < 7; k++) m = fmaxf(m, hm[ro + k][co]);
        float c = rts[ro + 3][co + 3];
        out[(by0 + ro) * W + bx0 + co] = (c == m) ? c : 0.f;
    }
}

// ---------------- launcher ------------------------------------------------
extern "C" void kernel_launch(void* const* d_in, const int* in_sizes, int n_in,
                              void* d_out, int out_size) {
    const float* x  = (const float*)d_in[0];
    const float* gk = (const float*)d_in[1];
    float* out = (float*)d_out;

    dim3 grd(W / TS, H / TS);

    init_kernel<<<2, 1024>>>();
    harris_R_kernel<<<grd, dim3(32, 4)>>>(x, gk);
    scan_select_kernel<<<1, 1024>>>(1);
    hist2_kernel<<<1024, 256>>>();
    scan_select_kernel<<<1, 1024>>>(2);
    hist3_kernel<<<1024, 256>>>();
    scan_select_kernel<<<1, 1024>>>(3);
    nms_kernel<<<grd, dim3(32, 8)>>>(out);
}

// round 11
// speedup vs baseline: 2.0715x; 1.0338x over previous
#include <cuda_runtime.h>
#include <stdint.h>

#define W 4096
#define H 4096
#define NPIX (W*H)
#define TS 32
#define XS 40   // TS + 2*4 (sobel halo 1 + gauss halo 3)
#define PS 38   // TS + 2*3
#define RANK0 8388607u  // (NPIX-1)/2

// ---------------- device scratch (no allocations allowed) ----------------
__device__ float g_R[NPIX];                 // Harris response, 64MB
__device__ unsigned int g_hist1[2048];
__device__ unsigned int g_hist2[2048];
__device__ unsigned int g_hist3[1024];
__device__ unsigned int g_bin1, g_bin2;
__device__ unsigned int g_rka, g_rkb;
__device__ float g_med;

// monotone float -> uint key (ascending IEEE order)
__device__ __forceinline__ unsigned int fkey(float f) {
    unsigned int u = __float_as_uint(f);
    return (u & 0x80000000u) ? ~u : (u | 0x80000000u);
}
__device__ __forceinline__ float keyf(unsigned int k) {
    unsigned int u = (k & 0x80000000u) ? (k & 0x7FFFFFFFu) : ~k;
    return __uint_as_float(u);
}

// ---------------- init: zero histograms (graph replays must reset) -------
__global__ void init_kernel() {
    int t = blockIdx.x * blockDim.x + threadIdx.x;
    if (t < 2048) { g_hist1[t] = 0u; g_hist2[t] = 0u; }
    if (t < 1024) g_hist3[t] = 0u;
}

// ---------------- K1: Sobel + products + direct 7x7 Gaussian + R ---------
// Numerics mimic XLA-CPU/Eigen: per-output sequential FMA chain over taps in
// row-major (kh outer, kw inner) order; elementwise ops with explicit _rn
// intrinsics. (Proven R3 configuration.)
__global__ __launch_bounds__(256) void harris_R_kernel(
    const float* __restrict__ x, const float* __restrict__ gk)
{
    __shared__ float xs[XS][XS];
    __shared__ float pch[3][PS][PS];
    __shared__ float gws[49];
    __shared__ unsigned int shist[2048];

    const int tid = threadIdx.y * 32 + threadIdx.x;
    const int bx0 = blockIdx.x * TS, by0 = blockIdx.y * TS;

    for (int i = tid; i < 2048; i += 256) shist[i] = 0u;
    if (tid < 49) gws[tid] = gk[tid];

    // load x tile with halo 4, zero outside image (conv zero padding)
    for (int i = tid; i < XS * XS; i += 256) {
        int r = i / XS, c = i % XS;
        int gr = by0 - 4 + r, gc = bx0 - 4 + c;
        float v = 0.f;
        if (gr >= 0 && gr < H && gc >= 0 && gc < W) v = x[gr * W + gc];
        xs[r][c] = v;
    }
    __syncthreads();

    // Sobel (sequential row-major tap chains) + products over tile + halo 3.
    for (int i = tid; i < PS * PS; i += 256) {
        int pr = i / PS, pc = i % PS;
        int gr = by0 - 3 + pr, gc = bx0 - 3 + pc;
        float a = 0.f, b = 0.f, ab = 0.f;
        if (gr >= 0 && gr < H && gc >= 0 && gc < W) {
            int r = pr + 1, c = pc + 1;
            float x00 = xs[r-1][c-1], x01 = xs[r-1][c], x02 = xs[r-1][c+1];
            float x10 = xs[r  ][c-1],                  x12 = xs[r  ][c+1];
            float x20 = xs[r+1][c-1], x21 = xs[r+1][c], x22 = xs[r+1][c+1];
            float ix = -x00;
            ix = __fmaf_rn( 1.f, x02, ix);
            ix = __fmaf_rn(-2.f, x10, ix);
            ix = __fmaf_rn( 2.f, x12, ix);
            ix = __fmaf_rn(-1.f, x20, ix);
            ix = __fmaf_rn( 1.f, x22, ix);
            float iy = -x00;
            iy = __fmaf_rn(-2.f, x01, iy);
            iy = __fmaf_rn(-1.f, x02, iy);
            iy = __fmaf_rn( 1.f, x20, iy);
            iy = __fmaf_rn( 2.f, x21, iy);
            iy = __fmaf_rn( 1.f, x22, iy);
            a  = __fmul_rn(ix, ix);
            b  = __fmul_rn(iy, iy);
            ab = __fmul_rn(ix, iy);
        }
        pch[0][pr][pc] = a; pch[1][pr][pc] = b; pch[2][pr][pc] = ab;
    }
    __syncthreads();

    // Direct 7x7 conv, 4 output rows per thread, sliding 4-row register ring.
    // Chain per output: kh outer (0..6), kw inner (0..6) — sequential FMAs.
    const int co = threadIdx.x;
    const int ro = threadIdx.y * 4;
    float S[3][4];

    #pragma unroll
    for (int ch = 0; ch < 3; ch++) {
        float acc[4] = {0.f, 0.f, 0.f, 0.f};
        float rb[4][7];
        #pragma unroll
        for (int o = 0; o < 4; o++)
            #pragma unroll
            for (int k = 0; k < 7; k++)
                rb[o][k] = pch[ch][ro + o][co + k];

        #pragma unroll
        for (int kh = 0; kh < 7; kh++) {
            if (kh > 0) {
                const int slot = (kh + 3) & 3;
                #pragma unroll
                for (int k = 0; k < 7; k++)
                    rb[slot][k] = pch[ch][ro + kh + 3][co + k];
            }
            #pragma unroll
            for (int kw = 0; kw < 7; kw++) {
                const float w = gws[kh * 7 + kw];
                #pragma unroll
                for (int o = 0; o < 4; o++)
                    acc[o] = __fmaf_rn(w, rb[(kh + o) & 3][kw], acc[o]);
            }
        }
        #pragma unroll
        for (int o = 0; o < 4; o++) S[ch][o] = acc[o];
    }

    #pragma unroll
    for (int o = 0; o < 4; o++) {
        float s0 = S[0][o], s1 = S[1][o], s2 = S[2][o];
        float tr = __fadd_rn(s0, s1);
        float t1 = __fmul_rn(s0, s1);
        float t2 = __fmul_rn(s2, s2);
        float t3 = __fmul_rn(__fmul_rn(0.05f, tr), tr);
        float R  = __fsub_rn(__fsub_rn(t1, t2), t3);
        g_R[(by0 + ro + o) * W + bx0 + co] = R;
        atomicAdd(&shist[fkey(R) >> 21], 1u);
    }
    __syncthreads();
    for (int i = tid; i < 2048; i += 256) {
        unsigned int v = shist[i];
        if (v) atomicAdd(&g_hist1[i], v);
    }
}

// ---------------- median radix-select passes -----------------------------
// Static partition: 1024 blocks x 256 threads x 16 float4 = NPIX/4 exactly.
// 4 independent LDG.128 issued per batch (MLP>=4), no bounds checks.
__device__ __forceinline__ void h2_elem(float f, unsigned int b1,
                                        unsigned int* sh) {
    unsigned int k = fkey(f);
    if ((k >> 21) == b1) atomicAdd(&sh[(k >> 10) & 2047u], 1u);
}

__global__ __launch_bounds__(256) void hist2_kernel() {
    __shared__ unsigned int sh[2048];
    const int tid = threadIdx.x;
    for (int i = tid; i < 2048; i += 256) sh[i] = 0u;
    __syncthreads();
    const unsigned int b1 = g_bin1;
    const float4* R4 = (const float4*)g_R;
    const int t0 = blockIdx.x * 4096 + tid;

    #pragma unroll
    for (int jj = 0; jj < 4; jj++) {
        float4 v0 = R4[t0 + (jj * 4 + 0) * 256];
        float4 v1 = R4[t0 + (jj * 4 + 1) * 256];
        float4 v2 = R4[t0 + (jj * 4 + 2) * 256];
        float4 v3 = R4[t0 + (jj * 4 + 3) * 256];
        h2_elem(v0.x, b1, sh); h2_elem(v0.y, b1, sh);
        h2_elem(v0.z, b1, sh); h2_elem(v0.w, b1, sh);
        h2_elem(v1.x, b1, sh); h2_elem(v1.y, b1, sh);
        h2_elem(v1.z, b1, sh); h2_elem(v1.w, b1, sh);
        h2_elem(v2.x, b1, sh); h2_elem(v2.y, b1, sh);
        h2_elem(v2.z, b1, sh); h2_elem(v2.w, b1, sh);
        h2_elem(v3.x, b1, sh); h2_elem(v3.y, b1, sh);
        h2_elem(v3.z, b1, sh); h2_elem(v3.w, b1, sh);
    }
    __syncthreads();
    for (int i = tid; i < 2048; i += 256) {
        unsigned int v = sh[i];
        if (v) atomicAdd(&g_hist2[i], v);
    }
}

__device__ __forceinline__ void h3_elem(float f, unsigned int p22,
                                        unsigned int* sh) {
    unsigned int k = fkey(f);
    if ((k >> 10) == p22) atomicAdd(&sh[k & 1023u], 1u);
}

__global__ __launch_bounds__(256) void hist3_kernel() {
    __shared__ unsigned int sh[1024];
    const int tid = threadIdx.x;
    for (int i = tid; i < 1024; i += 256) sh[i] = 0u;
    __syncthreads();
    const unsigned int p22 = (g_bin1 << 11) | g_bin2;
    const float4* R4 = (const float4*)g_R;
    const int t0 = blockIdx.x * 4096 + tid;

    #pragma unroll
    for (int jj = 0; jj < 4; jj++) {
        float4 v0 = R4[t0 + (jj * 4 + 0) * 256];
        float4 v1 = R4[t0 + (jj * 4 + 1) * 256];
        float4 v2 = R4[t0 + (jj * 4 + 2) * 256];
        float4 v3 = R4[t0 + (jj * 4 + 3) * 256];
        h3_elem(v0.x, p22, sh); h3_elem(v0.y, p22, sh);
        h3_elem(v0.z, p22, sh); h3_elem(v0.w, p22, sh);
        h3_elem(v1.x, p22, sh); h3_elem(v1.y, p22, sh);
        h3_elem(v1.z, p22, sh); h3_elem(v1.w, p22, sh);
        h3_elem(v2.x, p22, sh); h3_elem(v2.y, p22, sh);
        h3_elem(v2.z, p22, sh); h3_elem(v2.w, p22, sh);
        h3_elem(v3.x, p22, sh); h3_elem(v3.y, p22, sh);
        h3_elem(v3.z, p22, sh); h3_elem(v3.w, p22, sh);
    }
    __syncthreads();
    for (int i = tid; i < 1024; i += 256) {
        unsigned int v = sh[i];
        if (v) atomicAdd(&g_hist3[i], v);
    }
}

// scan a histogram in parallel, select the bin containing the residual rank
__global__ __launch_bounds__(1024) void scan_select_kernel(int pass) {
    __shared__ unsigned int ss[1024];
    int t = threadIdx.x;
    const unsigned int* hist;
    int nbins;
    if (pass == 1)      { hist = g_hist1; nbins = 2048; }
    else if (pass == 2) { hist = g_hist2; nbins = 2048; }
    else                { hist = g_hist3; nbins = 1024; }
    int bpt = nbins >> 10;  // 2 or 1
    unsigned int local = 0u;
    for (int i = 0; i < bpt; i++) local += hist[t * bpt + i];
    ss[t] = local;
    __syncthreads();
    for (int off = 1; off < 1024; off <<= 1) {
        unsigned int v = (t >= off) ? ss[t - off] : 0u;
        __syncthreads();
        ss[t] += v;
        __syncthreads();
    }
    unsigned int rank = (pass == 1) ? RANK0 : ((pass == 2) ? g_rka : g_rkb);
    unsigned int cb = (t == 0) ? 0u : ss[t - 1];
    for (int i = 0; i < bpt; i++) {
        unsigned int hv = hist[t * bpt + i];
        if (rank >= cb && rank < cb + hv) {
            unsigned int bin = (unsigned int)(t * bpt + i);
            if (pass == 1)      { g_bin1 = bin; g_rka = rank - cb; }
            else if (pass == 2) { g_bin2 = bin; g_rkb = rank - cb; }
            else {
                unsigned int key = (g_bin1 << 21) | (g_bin2 << 10) | bin;
                g_med = keyf(key);
            }
        }
        cb += hv;
    }
}

// ---------------- threshold + 7x7 max-pool NMS ---------------------------
#define MS 38
__global__ __launch_bounds__(256) void nms_kernel(float* __restrict__ out) {
    __shared__ float rts[MS][MS + 1];
    __shared__ float hm[MS][TS];
    const int tid = threadIdx.y * 32 + threadIdx.x;
    const int bx0 = blockIdx.x * TS, by0 = blockIdx.y * TS;
    const float med = g_med;
    const float NEGINF = __int_as_float(0xff800000);

    for (int i = tid; i < MS * MS; i += 256) {
        int r = i / MS, c = i % MS;
        int gr = by0 - 3 + r, gc = bx0 - 3 + c;
        float v = NEGINF;
        if (gr >= 0 && gr < H && gc >= 0 && gc < W) {
            float R = g_R[gr * W + gc];
            v = (R < med) ? 0.f : R;
        }
        rts[r][c] = v;
    }
    __syncthreads();

    for (int i = tid; i < MS * TS; i += 256) {
        int r = i / TS, co = i % TS;
        float m = rts[r][co];
        #pragma unroll
        for (int k = 1; k < 7; k++) m = fmaxf(m, rts[r][co + k]);
        hm[r][co] = m;
    }
    __syncthreads();

    for (int ro = threadIdx.y; ro < TS; ro += 8) {
        int co = threadIdx.x;
        float m = hm[ro][co];
        #pragma unroll
        for (int k = 1; k < 7; k++) m = fmaxf(m, hm[ro + k][co]);
        float c = rts[ro + 3][co + 3];
        out[(by0 + ro) * W + bx0 + co] = (c == m) ? c : 0.f;
    }
}

// ---------------- launcher ------------------------------------------------
extern "C" void kernel_launch(void* const* d_in, const int* in_sizes, int n_in,
                              void* d_out, int out_size) {
    const float* x  = (const float*)d_in[0];
    const float* gk = (const float*)d_in[1];
    float* out = (float*)d_out;

    dim3 blk(32, 8);
    dim3 grd(W / TS, H / TS);

    init_kernel<<<2, 1024>>>();
    harris_R_kernel<<<grd, blk>>>(x, gk);
    scan_select_kernel<<<1, 1024>>>(1);
    hist2_kernel<<<1024, 256>>>();
    scan_select_kernel<<<1, 1024>>>(2);
    hist3_kernel<<<1024, 256>>>();
    scan_select_kernel<<<1, 1024>>>(3);
    nms_kernel<<<grd, blk>>>(out);
}